// round 7
// baseline (speedup 1.0000x reference)
#include <cuda_runtime.h>

#define N_USERS 100000
#define N_ITEMS 50000
#define N_NODES 150000
#define KDIM    64
#define N_EDGES 2000000
#define BATCH   4096
#define NEG_SLOPE 0.01f
#define EPSV    1e-12f

#define SCAN_ELEMS 4096
#define SCAN_BLOCKS ((N_NODES + SCAN_ELEMS - 1) / SCAN_ELEMS)   // 37

#define NCH      4
#define CH_NODES 37504     // 64-aligned chunk; last chunk is shorter

typedef unsigned long long u64;

__device__ __forceinline__ u64 dup2(float v) {
    u64 r; asm("mov.b64 %0, {%1, %1};" : "=l"(r) : "f"(v)); return r;
}
__device__ __forceinline__ u64 pack2(float lo, float hi) {
    u64 r; asm("mov.b64 %0, {%1, %2};" : "=l"(r) : "f"(lo), "f"(hi)); return r;
}
__device__ __forceinline__ float2 unpack2(u64 v) {
    float2 f; asm("mov.b64 {%0, %1}, %2;" : "=f"(f.x), "=f"(f.y) : "l"(v)); return f;
}
__device__ __forceinline__ void fma2(u64& d, u64 a, u64 b) {
    asm("fma.rn.f32x2 %0, %1, %2, %0;" : "+l"(d) : "l"(a), "l"(b));
}

// ---------------- scratch ----------------------------------------------------
__device__ float g_X[(size_t)N_NODES * KDIM];
__device__ float g_Y[(size_t)N_NODES * KDIM];
__device__ float g_S[(size_t)N_NODES * KDIM];
__device__ float g_wsum[N_NODES];
__device__ int   g_cnt[N_NODES];
__device__ int   g_off[N_NODES + 1];
__device__ int   g_fill[N_NODES];
__device__ int2  g_edge[N_EDGES];
__device__ int   g_part[SCAN_BLOCKS];
__device__ int   g_partoff[SCAN_BLOCKS];

// ---------------- init: X = concat(Gu, Gi); zero counters ------------------
__global__ void k_init(const float* __restrict__ Gu, const float* __restrict__ Gi) {
    int i = blockIdx.x * blockDim.x + threadIdx.x;
    const int total  = N_NODES * KDIM / 4;
    const int usplit = N_USERS * KDIM / 4;
    if (i < N_NODES) g_cnt[i] = 0;
    if (i >= total) return;
    float4 v = (i < usplit) ? ((const float4*)Gu)[i] : ((const float4*)Gi)[i - usplit];
    ((float4*)g_X)[i] = v;
}

// ---------------- CSR build -------------------------------------------------
__global__ void k_hist(const int* __restrict__ dst) {
    int t = blockIdx.x * blockDim.x + threadIdx.x;
    int e = t * 4;
    if (e + 3 < N_EDGES) {
        int4 d4 = *(const int4*)&dst[e];
        atomicAdd(&g_cnt[d4.x], 1);
        atomicAdd(&g_cnt[d4.y], 1);
        atomicAdd(&g_cnt[d4.z], 1);
        atomicAdd(&g_cnt[d4.w], 1);
    } else {
        for (int i = e; i < N_EDGES; i++) atomicAdd(&g_cnt[dst[i]], 1);
    }
}

__global__ void __launch_bounds__(1024) k_part() {
    __shared__ int red[32];
    int tid = threadIdx.x;
    int base = blockIdx.x * SCAN_ELEMS + tid * 4;
    int s = 0;
#pragma unroll
    for (int j = 0; j < 4; j++) {
        int g = base + j;
        s += (g < N_NODES) ? g_cnt[g] : 0;
    }
#pragma unroll
    for (int o = 16; o; o >>= 1) s += __shfl_xor_sync(0xffffffffu, s, o);
    if ((tid & 31) == 0) red[tid >> 5] = s;
    __syncthreads();
    if (tid < 32) {
        int v = red[tid];
#pragma unroll
        for (int o = 16; o; o >>= 1) v += __shfl_xor_sync(0xffffffffu, v, o);
        if (tid == 0) g_part[blockIdx.x] = v;
    }
}

__global__ void k_scanpart() {
    __shared__ int s[64];
    int tid = threadIdx.x;
    int v = (tid < SCAN_BLOCKS) ? g_part[tid] : 0;
    s[tid] = v;
    __syncthreads();
#pragma unroll
    for (int o = 1; o < 64; o <<= 1) {
        int t = (tid >= o) ? s[tid - o] : 0;
        __syncthreads();
        s[tid] += t;
        __syncthreads();
    }
    if (tid < SCAN_BLOCKS) g_partoff[tid] = s[tid] - v;
    if (tid == 63) g_off[N_NODES] = s[63];
}

__global__ void __launch_bounds__(1024) k_scanfinal() {
    __shared__ int wsm[33];
    int tid = threadIdx.x;
    int lane = tid & 31, wid = tid >> 5;
    int base = blockIdx.x * SCAN_ELEMS + tid * 4;
    int v[4];
    int t = 0;
#pragma unroll
    for (int j = 0; j < 4; j++) {
        int g = base + j;
        v[j] = (g < N_NODES) ? g_cnt[g] : 0;
        t += v[j];
    }
    int inc = t;
#pragma unroll
    for (int o = 1; o < 32; o <<= 1) {
        int u = __shfl_up_sync(0xffffffffu, inc, o);
        if (lane >= o) inc += u;
    }
    if (lane == 31) wsm[wid] = inc;
    __syncthreads();
    if (wid == 0) {
        int w = wsm[lane];
        int wi = w;
#pragma unroll
        for (int o = 1; o < 32; o <<= 1) {
            int u = __shfl_up_sync(0xffffffffu, wi, o);
            if (lane >= o) wi += u;
        }
        wsm[lane] = wi - w;
    }
    __syncthreads();
    int excl = g_partoff[blockIdx.x] + wsm[wid] + inc - t;
#pragma unroll
    for (int j = 0; j < 4; j++) {
        int g = base + j;
        if (g < N_NODES) { g_off[g] = excl; g_fill[g] = excl; }
        excl += v[j];
    }
}

__global__ void k_fill(const int* __restrict__ src, const int* __restrict__ dst,
                       const float* __restrict__ ew) {
    int t = blockIdx.x * blockDim.x + threadIdx.x;
    int e = t * 4;
    if (e + 3 < N_EDGES) {
        int4   s4 = *(const int4*)&src[e];
        int4   d4 = *(const int4*)&dst[e];
        float4 w4 = *(const float4*)&ew[e];
        int p0 = atomicAdd(&g_fill[d4.x], 1);
        int p1 = atomicAdd(&g_fill[d4.y], 1);
        int p2 = atomicAdd(&g_fill[d4.z], 1);
        int p3 = atomicAdd(&g_fill[d4.w], 1);
        g_edge[p0] = make_int2(s4.x, __float_as_int(w4.x));
        g_edge[p1] = make_int2(s4.y, __float_as_int(w4.y));
        g_edge[p2] = make_int2(s4.z, __float_as_int(w4.z));
        g_edge[p3] = make_int2(s4.w, __float_as_int(w4.w));
    } else {
        for (int i = e; i < N_EDGES; i++) {
            int p = atomicAdd(&g_fill[dst[i]], 1);
            g_edge[p] = make_int2(src[i], __float_as_int(ew[i]));
        }
    }
}

// ---------------- per-layer gather (chunked) --------------------------------
__global__ void k_gather(int insel, int nbase, int nend) {
    const float* __restrict__ X = insel ? g_Y : g_X;
    int gthr = blockIdx.x * blockDim.x + threadIdx.x;
    int n = nbase + (gthr >> 5);
    if (n >= nend) return;
    int lane = threadIdx.x & 31;
    int b = g_off[n], e = g_off[n + 1];
    float ax = 0.0f, ay = 0.0f, wa = 0.0f;
    int i = b;
    for (; i + 3 < e; i += 4) {
        int2 E0 = g_edge[i];
        int2 E1 = g_edge[i + 1];
        int2 E2 = g_edge[i + 2];
        int2 E3 = g_edge[i + 3];
        float2 v0 = *(const float2*)&X[(size_t)E0.x * KDIM + lane * 2];
        float2 v1 = *(const float2*)&X[(size_t)E1.x * KDIM + lane * 2];
        float2 v2 = *(const float2*)&X[(size_t)E2.x * KDIM + lane * 2];
        float2 v3 = *(const float2*)&X[(size_t)E3.x * KDIM + lane * 2];
        float w0 = __int_as_float(E0.y), w1 = __int_as_float(E1.y);
        float w2 = __int_as_float(E2.y), w3 = __int_as_float(E3.y);
        ax += w0 * v0.x + w1 * v1.x + w2 * v2.x + w3 * v3.x;
        ay += w0 * v0.y + w1 * v1.y + w2 * v2.y + w3 * v3.y;
        wa += w0 + w1 + w2 + w3;
    }
    for (; i < e; i++) {
        int2 E0 = g_edge[i];
        float w0 = __int_as_float(E0.y);
        float2 v0 = *(const float2*)&X[(size_t)E0.x * KDIM + lane * 2];
        ax += w0 * v0.x;
        ay += w0 * v0.y;
        wa += w0;
    }
    *(float2*)&g_S[(size_t)n * KDIM + lane * 2] = make_float2(ax, ay);
    if (insel == 0 && lane == 0) g_wsum[n] = wa;
}

// ---------------- per-layer update (chunked) --------------------------------
#define ROWP 66
__global__ void __launch_bounds__(128) k_update(
    const float* __restrict__ W1, const float* __restrict__ b1,
    const float* __restrict__ W2, const float* __restrict__ b2,
    int l, int nbase, int nend) {
    __shared__ float sA[64 * ROWP];
    __shared__ float sB[64 * ROWP];
    const float* __restrict__ Xin = (l & 1) ? g_Y : g_X;
    float* __restrict__ Yout      = (l & 1) ? g_X : g_Y;

    int tid = threadIdx.x;
    int grp = tid >> 4;
    int t16 = tid & 15;
    int node0 = nbase + blockIdx.x * 64;
    int nb = grp * 8;
    int c = t16 * 4;

    const float* W1l = W1 + l * 4096;
    const float* W2l = W2 + l * 4096;

#pragma unroll
    for (int m = 0; m < 8; m++) {
        int nl = nb + m;
        int n = node0 + nl;
        if (n < nend) {
            float4 sv = *(const float4*)&g_S[(size_t)n * KDIM + c];
            float4 xv = *(const float4*)&Xin[(size_t)n * KDIM + c];
            sA[(c + 0) * ROWP + nl] = sv.x + xv.x;
            sA[(c + 1) * ROWP + nl] = sv.y + xv.y;
            sA[(c + 2) * ROWP + nl] = sv.z + xv.z;
            sA[(c + 3) * ROWP + nl] = sv.w + xv.w;
            sB[(c + 0) * ROWP + nl] = sv.x * xv.x;
            sB[(c + 1) * ROWP + nl] = sv.y * xv.y;
            sB[(c + 2) * ROWP + nl] = sv.z * xv.z;
            sB[(c + 3) * ROWP + nl] = sv.w * xv.w;
        } else {
            sA[(c + 0) * ROWP + nl] = 0.0f;
            sA[(c + 1) * ROWP + nl] = 0.0f;
            sA[(c + 2) * ROWP + nl] = 0.0f;
            sA[(c + 3) * ROWP + nl] = 0.0f;
            sB[(c + 0) * ROWP + nl] = 0.0f;
            sB[(c + 1) * ROWP + nl] = 0.0f;
            sB[(c + 2) * ROWP + nl] = 0.0f;
            sB[(c + 3) * ROWP + nl] = 0.0f;
        }
    }
    __syncwarp();

    float4 B1 = __ldg((const float4*)&b1[l * 64 + c]);
    float4 B2 = __ldg((const float4*)&b2[l * 64 + c]);

    u64 acc[4][4];
#pragma unroll
    for (int p = 0; p < 4; p++) {
        int n0 = node0 + nb + 2 * p;
        float w0 = (n0 < nend) ? g_wsum[n0] : 0.0f;
        float w1 = (n0 + 1 < nend) ? g_wsum[n0 + 1] : 0.0f;
        acc[p][0] = pack2((w0 + 1.0f) * B1.x + w0 * B2.x, (w1 + 1.0f) * B1.x + w1 * B2.x);
        acc[p][1] = pack2((w0 + 1.0f) * B1.y + w0 * B2.y, (w1 + 1.0f) * B1.y + w1 * B2.y);
        acc[p][2] = pack2((w0 + 1.0f) * B1.z + w0 * B2.z, (w1 + 1.0f) * B1.z + w1 * B2.z);
        acc[p][3] = pack2((w0 + 1.0f) * B1.w + w0 * B2.w, (w1 + 1.0f) * B1.w + w1 * B2.w);
    }

#pragma unroll 2
    for (int k = 0; k < 64; k++) {
        float4 w1 = __ldg((const float4*)&W1l[k * 64 + c]);
        float4 w2 = __ldg((const float4*)&W2l[k * 64 + c]);
        u64 d10 = dup2(w1.x), d11 = dup2(w1.y), d12 = dup2(w1.z), d13 = dup2(w1.w);
        u64 d20 = dup2(w2.x), d21 = dup2(w2.y), d22 = dup2(w2.z), d23 = dup2(w2.w);
        const float* ra = &sA[k * ROWP + nb];
        const float* rb = &sB[k * ROWP + nb];
#pragma unroll
        for (int p = 0; p < 4; p++) {
            u64 ap = *(const u64*)&ra[2 * p];
            u64 bp = *(const u64*)&rb[2 * p];
            fma2(acc[p][0], ap, d10);
            fma2(acc[p][1], ap, d11);
            fma2(acc[p][2], ap, d12);
            fma2(acc[p][3], ap, d13);
            fma2(acc[p][0], bp, d20);
            fma2(acc[p][1], bp, d21);
            fma2(acc[p][2], bp, d22);
            fma2(acc[p][3], bp, d23);
        }
    }

#pragma unroll
    for (int p = 0; p < 4; p++) {
        float2 y[4];
#pragma unroll
        for (int j = 0; j < 4; j++) {
            float2 v = unpack2(acc[p][j]);
            y[j].x = v.x > 0.0f ? v.x : NEG_SLOPE * v.x;
            y[j].y = v.y > 0.0f ? v.y : NEG_SLOPE * v.y;
        }
        float ssx = y[0].x * y[0].x + y[1].x * y[1].x + y[2].x * y[2].x + y[3].x * y[3].x;
        float ssy = y[0].y * y[0].y + y[1].y * y[1].y + y[2].y * y[2].y + y[3].y * y[3].y;
#pragma unroll
        for (int o = 1; o < 16; o <<= 1) {
            ssx += __shfl_xor_sync(0xffffffffu, ssx, o);
            ssy += __shfl_xor_sync(0xffffffffu, ssy, o);
        }
        float inv0 = 1.0f / fmaxf(sqrtf(ssx), EPSV);
        float inv1 = 1.0f / fmaxf(sqrtf(ssy), EPSV);
        int n0 = node0 + nb + 2 * p;
        if (n0 < nend)
            *(float4*)&Yout[(size_t)n0 * KDIM + c] =
                make_float4(y[0].x * inv0, y[1].x * inv0, y[2].x * inv0, y[3].x * inv0);
        if (n0 + 1 < nend)
            *(float4*)&Yout[(size_t)(n0 + 1) * KDIM + c] =
                make_float4(y[0].y * inv1, y[1].y * inv1, y[2].y * inv1, y[3].y * inv1);
    }
}

// ---------------- incremental batch dot ------------------------------------
__global__ void k_dot(const int* __restrict__ user, const int* __restrict__ pos,
                      float* __restrict__ out, int sel, int first) {
    const float* __restrict__ X = sel ? g_Y : g_X;
    int gthr = blockIdx.x * blockDim.x + threadIdx.x;
    int w = gthr >> 5;
    if (w >= BATCH) return;
    int lane = threadIdx.x & 31;
    int u  = user[w];
    int it = pos[w];
    float2 a = *(const float2*)&X[(size_t)u * KDIM + lane * 2];
    float2 b = *(const float2*)&X[((size_t)N_USERS + it) * KDIM + lane * 2];
    float d = a.x * b.x + a.y * b.y;
    d += __shfl_xor_sync(0xffffffffu, d, 16);
    d += __shfl_xor_sync(0xffffffffu, d, 8);
    d += __shfl_xor_sync(0xffffffffu, d, 4);
    d += __shfl_xor_sync(0xffffffffu, d, 2);
    d += __shfl_xor_sync(0xffffffffu, d, 1);
    if (lane == 0) out[w] = first ? d : out[w] + d;
}

// ---------------- launch ----------------------------------------------------
extern "C" void kernel_launch(void* const* d_in, const int* in_sizes, int n_in,
                              void* d_out, int out_size) {
    const float* Gu   = (const float*)d_in[0];
    const float* Gi   = (const float*)d_in[1];
    const float* W1   = (const float*)d_in[2];
    const float* b1   = (const float*)d_in[3];
    const float* W2   = (const float*)d_in[4];
    const float* b2   = (const float*)d_in[5];
    const float* ew   = (const float*)d_in[6];
    const int*   esrc = (const int*)d_in[7];
    const int*   edst = (const int*)d_in[8];
    const int*   user = (const int*)d_in[9];
    const int*   pos  = (const int*)d_in[10];
    float* out = (float*)d_out;

    // lazy host-resource init (first call = uncaptured correctness run)
    static cudaStream_t sU = 0;
    static cudaEvent_t evInit, evDone, evG[3][NCH], evU[2];
    static int inited = 0;
    if (!inited) {
        inited = 1;
        cudaStreamCreateWithFlags(&sU, cudaStreamNonBlocking);
        cudaEventCreateWithFlags(&evInit, cudaEventDisableTiming);
        cudaEventCreateWithFlags(&evDone, cudaEventDisableTiming);
        for (int l = 0; l < 3; l++)
            for (int c = 0; c < NCH; c++)
                cudaEventCreateWithFlags(&evG[l][c], cudaEventDisableTiming);
        for (int l = 0; l < 2; l++)
            cudaEventCreateWithFlags(&evU[l], cudaEventDisableTiming);
    }

    const int TB = 256;
    const int GBLK = (CH_NODES * 32 + TB - 1) / TB;   // gather blocks per chunk
    const int UBLK = CH_NODES / 64;                    // update blocks per chunk

    // prelude on capture stream
    k_init<<<(N_NODES * KDIM / 4 + TB - 1) / TB, TB>>>(Gu, Gi);
    cudaEventRecord(evInit, 0);
    k_hist<<<(N_EDGES / 4 + TB - 1) / TB, TB>>>(edst);
    k_part<<<SCAN_BLOCKS, 1024>>>();
    k_scanpart<<<1, 64>>>();
    k_scanfinal<<<SCAN_BLOCKS, 1024>>>();
    k_fill<<<(N_EDGES / 4 + TB - 1) / TB, TB>>>(esrc, edst, ew);

    // layer-0 dot on worker stream (needs only init)
    cudaStreamWaitEvent(sU, evInit, 0);
    k_dot<<<(BATCH * 32 + TB - 1) / TB, TB, 0, sU>>>(user, pos, out, 0, 1);

    for (int l = 0; l < 3; l++) {
        int insel  = l & 1;
        int outsel = insel ^ 1;
        if (l > 0) cudaStreamWaitEvent((cudaStream_t)0, evU[l - 1], 0);
        for (int c = 0; c < NCH; c++) {
            int nbase = c * CH_NODES;
            int nend  = (nbase + CH_NODES < N_NODES) ? nbase + CH_NODES : N_NODES;
            k_gather<<<GBLK, TB>>>(insel, nbase, nend);
            cudaEventRecord(evG[l][c], 0);
        }
        for (int c = 0; c < NCH; c++) {
            int nbase = c * CH_NODES;
            int nend  = (nbase + CH_NODES < N_NODES) ? nbase + CH_NODES : N_NODES;
            cudaStreamWaitEvent(sU, evG[l][c], 0);
            k_update<<<UBLK, 128, 0, sU>>>(W1, b1, W2, b2, l, nbase, nend);
        }
        if (l < 2) cudaEventRecord(evU[l], sU);
        k_dot<<<(BATCH * 32 + TB - 1) / TB, TB, 0, sU>>>(user, pos, out, outsel, 0);
    }

    cudaEventRecord(evDone, sU);
    cudaStreamWaitEvent((cudaStream_t)0, evDone, 0);
}

// round 8
// speedup vs baseline: 1.0635x; 1.0635x over previous
#include <cuda_runtime.h>

#define N_USERS 100000
#define N_ITEMS 50000
#define N_NODES 150000
#define KDIM    64
#define N_EDGES 2000000
#define BATCH   4096
#define NEG_SLOPE 0.01f
#define EPSV    1e-12f

#define SCAN_ELEMS 4096
#define SCAN_BLOCKS ((N_NODES + SCAN_ELEMS - 1) / SCAN_ELEMS)   // 37

#define GB_GATHER ((N_NODES * 32) / 256)          // 18750 gather blocks
#define DOT_BLOCKS (BATCH / 8)                     // 512 dot blocks (8 warps each)

typedef unsigned long long u64;

__device__ __forceinline__ u64 dup2(float v) {
    u64 r; asm("mov.b64 %0, {%1, %1};" : "=l"(r) : "f"(v)); return r;
}
__device__ __forceinline__ u64 pack2(float lo, float hi) {
    u64 r; asm("mov.b64 %0, {%1, %2};" : "=l"(r) : "f"(lo), "f"(hi)); return r;
}
__device__ __forceinline__ float2 unpack2(u64 v) {
    float2 f; asm("mov.b64 {%0, %1}, %2;" : "=f"(f.x), "=f"(f.y) : "l"(v)); return f;
}
__device__ __forceinline__ void fma2(u64& d, u64 a, u64 b) {
    asm("fma.rn.f32x2 %0, %1, %2, %0;" : "+l"(d) : "l"(a), "l"(b));
}

// ---------------- scratch ----------------------------------------------------
__device__ float g_X[(size_t)N_NODES * KDIM];
__device__ float g_Y[(size_t)N_NODES * KDIM];
__device__ float g_S[(size_t)N_NODES * KDIM];
__device__ float g_wsum[N_NODES];
__device__ int   g_cnt[N_NODES];        // zeroed by scan kernel for next call
__device__ int   g_off[N_NODES + 1];
__device__ int   g_fill[N_NODES];
__device__ int2  g_edge[N_EDGES];
__device__ int   g_sflag[SCAN_BLOCKS];  // zeroed by k_init each call
__device__ int   g_spfx[SCAN_BLOCKS];

// ---------------- init: X = concat(Gu, Gi); zero scan flags ----------------
__global__ void k_init(const float* __restrict__ Gu, const float* __restrict__ Gi) {
    int i = blockIdx.x * blockDim.x + threadIdx.x;
    const int total  = N_NODES * KDIM / 4;
    const int usplit = N_USERS * KDIM / 4;
    if (i < SCAN_BLOCKS) g_sflag[i] = 0;
    if (i >= total) return;
    float4 v = (i < usplit) ? ((const float4*)Gu)[i] : ((const float4*)Gi)[i - usplit];
    ((float4*)g_X)[i] = v;
}

// ---------------- CSR build -------------------------------------------------
__global__ void k_hist(const int* __restrict__ dst) {
    int t = blockIdx.x * blockDim.x + threadIdx.x;
    int e = t * 4;
    if (e + 3 < N_EDGES) {
        int4 d4 = *(const int4*)&dst[e];
        atomicAdd(&g_cnt[d4.x], 1);
        atomicAdd(&g_cnt[d4.y], 1);
        atomicAdd(&g_cnt[d4.z], 1);
        atomicAdd(&g_cnt[d4.w], 1);
    } else {
        for (int i = e; i < N_EDGES; i++) atomicAdd(&g_cnt[dst[i]], 1);
    }
}

// single-pass chained scan: 37 blocks, all co-resident; exclusive prefix of
// g_cnt into g_off/g_fill; zeroes g_cnt behind itself (for the next call).
__global__ void __launch_bounds__(1024) k_scan37() {
    __shared__ int wsm[33];
    __shared__ int s_prefix;
    int b = blockIdx.x;
    int tid = threadIdx.x;
    int lane = tid & 31, wid = tid >> 5;
    int base = b * SCAN_ELEMS + tid * 4;

    int v[4];
    int t = 0;
#pragma unroll
    for (int j = 0; j < 4; j++) {
        int g = base + j;
        v[j] = (g < N_NODES) ? g_cnt[g] : 0;
        t += v[j];
    }
    int inc = t;
#pragma unroll
    for (int o = 1; o < 32; o <<= 1) {
        int u = __shfl_up_sync(0xffffffffu, inc, o);
        if (lane >= o) inc += u;
    }
    if (lane == 31) wsm[wid] = inc;
    __syncthreads();
    if (wid == 0) {
        int w = wsm[lane];
        int wi = w;
#pragma unroll
        for (int o = 1; o < 32; o <<= 1) {
            int u = __shfl_up_sync(0xffffffffu, wi, o);
            if (lane >= o) wi += u;
        }
        wsm[lane] = wi - w;   // exclusive warp offsets
        if (lane == 31) wsm[32] = wi;  // block total
    }
    __syncthreads();
    int btotal = wsm[32];

    // chained prefix
    if (tid == 0) {
        int prefix = 0;
        if (b > 0) {
            while (atomicAdd(&g_sflag[b - 1], 0) == 0) { }
            prefix = g_spfx[b - 1];
        }
        g_spfx[b] = prefix + btotal;
        __threadfence();
        atomicExch(&g_sflag[b], 1);
        s_prefix = prefix;
        if (b == SCAN_BLOCKS - 1) g_off[N_NODES] = prefix + btotal;
    }
    __syncthreads();

    int excl = s_prefix + wsm[wid] + inc - t;
#pragma unroll
    for (int j = 0; j < 4; j++) {
        int g = base + j;
        if (g < N_NODES) { g_off[g] = excl; g_fill[g] = excl; g_cnt[g] = 0; }
        excl += v[j];
    }
}

__global__ void k_fill(const int* __restrict__ src, const int* __restrict__ dst,
                       const float* __restrict__ ew) {
    int t = blockIdx.x * blockDim.x + threadIdx.x;
    int e = t * 4;
    if (e + 3 < N_EDGES) {
        int4   s4 = *(const int4*)&src[e];
        int4   d4 = *(const int4*)&dst[e];
        float4 w4 = *(const float4*)&ew[e];
        int p0 = atomicAdd(&g_fill[d4.x], 1);
        int p1 = atomicAdd(&g_fill[d4.y], 1);
        int p2 = atomicAdd(&g_fill[d4.z], 1);
        int p3 = atomicAdd(&g_fill[d4.w], 1);
        g_edge[p0] = make_int2(s4.x, __float_as_int(w4.x));
        g_edge[p1] = make_int2(s4.y, __float_as_int(w4.y));
        g_edge[p2] = make_int2(s4.z, __float_as_int(w4.z));
        g_edge[p3] = make_int2(s4.w, __float_as_int(w4.w));
    } else {
        for (int i = e; i < N_EDGES; i++) {
            int p = atomicAdd(&g_fill[dst[i]], 1);
            g_edge[p] = make_int2(src[i], __float_as_int(ew[i]));
        }
    }
}

// ---------------- gather (+ folded batch dot over the same input buffer) ---
// gather: 1 warp/node; half-warps serve alternating edges with float4 rows,
// halves merged by shfl_xor(16) at the end.
__global__ void k_gather(int insel, const int* __restrict__ user,
                         const int* __restrict__ pos, float* __restrict__ out,
                         int first) {
    const float* __restrict__ X = insel ? g_Y : g_X;
    int lane = threadIdx.x & 31;

    if (blockIdx.x >= GB_GATHER) {
        // folded dot: out[w] (+)= <emb[user], emb[pos]> over buffer X
        int w = (blockIdx.x - GB_GATHER) * 8 + (threadIdx.x >> 5);
        if (w >= BATCH) return;
        int u  = user[w];
        int it = pos[w];
        float2 a = *(const float2*)&X[(size_t)u * KDIM + lane * 2];
        float2 bb = *(const float2*)&X[((size_t)N_USERS + it) * KDIM + lane * 2];
        float d = a.x * bb.x + a.y * bb.y;
        d += __shfl_xor_sync(0xffffffffu, d, 16);
        d += __shfl_xor_sync(0xffffffffu, d, 8);
        d += __shfl_xor_sync(0xffffffffu, d, 4);
        d += __shfl_xor_sync(0xffffffffu, d, 2);
        d += __shfl_xor_sync(0xffffffffu, d, 1);
        if (lane == 0) out[w] = first ? d : out[w] + d;
        return;
    }

    int n = blockIdx.x * 8 + (threadIdx.x >> 5);
    if (n >= N_NODES) return;
    int half = lane >> 4;       // 0 or 1
    int hl   = lane & 15;       // column group: cols 4*hl .. 4*hl+3
    int b = g_off[n], e = g_off[n + 1];
    float4 acc = make_float4(0.f, 0.f, 0.f, 0.f);
    float wa = 0.0f;
    int i = b;
    for (; i + 3 < e; i += 4) {
        int2 E0 = g_edge[i];
        int2 E1 = g_edge[i + 1];
        int2 E2 = g_edge[i + 2];
        int2 E3 = g_edge[i + 3];
        int   r01 = half ? E1.x : E0.x;
        int   r23 = half ? E3.x : E2.x;
        float w01 = __int_as_float(half ? E1.y : E0.y);
        float w23 = __int_as_float(half ? E3.y : E2.y);
        float4 v0 = *(const float4*)&X[(size_t)r01 * KDIM + hl * 4];
        float4 v1 = *(const float4*)&X[(size_t)r23 * KDIM + hl * 4];
        acc.x += w01 * v0.x + w23 * v1.x;
        acc.y += w01 * v0.y + w23 * v1.y;
        acc.z += w01 * v0.z + w23 * v1.z;
        acc.w += w01 * v0.w + w23 * v1.w;
        wa += __int_as_float(E0.y) + __int_as_float(E1.y)
            + __int_as_float(E2.y) + __int_as_float(E3.y);
    }
    for (; i + 1 < e; i += 2) {
        int2 E0 = g_edge[i];
        int2 E1 = g_edge[i + 1];
        int   r01 = half ? E1.x : E0.x;
        float w01 = __int_as_float(half ? E1.y : E0.y);
        float4 v0 = *(const float4*)&X[(size_t)r01 * KDIM + hl * 4];
        acc.x += w01 * v0.x;
        acc.y += w01 * v0.y;
        acc.z += w01 * v0.z;
        acc.w += w01 * v0.w;
        wa += __int_as_float(E0.y) + __int_as_float(E1.y);
    }
    if (i < e) {
        int2 E0 = g_edge[i];
        float w0 = __int_as_float(E0.y);
        float4 v0 = *(const float4*)&X[(size_t)E0.x * KDIM + hl * 4];
        float w = half ? 0.0f : w0;
        acc.x += w * v0.x;
        acc.y += w * v0.y;
        acc.z += w * v0.z;
        acc.w += w * v0.w;
        wa += w0;
    }
    // merge the two halves
    acc.x += __shfl_xor_sync(0xffffffffu, acc.x, 16);
    acc.y += __shfl_xor_sync(0xffffffffu, acc.y, 16);
    acc.z += __shfl_xor_sync(0xffffffffu, acc.z, 16);
    acc.w += __shfl_xor_sync(0xffffffffu, acc.w, 16);
    if (half == 0)
        *(float4*)&g_S[(size_t)n * KDIM + hl * 4] = acc;
    if (insel == 0 && lane == 0) g_wsum[n] = wa;
}

// ---------------- per-layer: GEMM + bias + LeakyReLU + L2-normalize --------
#define ROWP 66
__global__ void __launch_bounds__(128) k_update(
    const float* __restrict__ W1, const float* __restrict__ b1,
    const float* __restrict__ W2, const float* __restrict__ b2,
    int l) {
    __shared__ float sA[64 * ROWP];
    __shared__ float sB[64 * ROWP];
    const float* __restrict__ Xin = (l & 1) ? g_Y : g_X;
    float* __restrict__ Yout      = (l & 1) ? g_X : g_Y;

    int tid = threadIdx.x;
    int grp = tid >> 4;
    int t16 = tid & 15;
    int node0 = blockIdx.x * 64;
    int nb = grp * 8;
    int c = t16 * 4;

    const float* W1l = W1 + l * 4096;
    const float* W2l = W2 + l * 4096;

#pragma unroll
    for (int m = 0; m < 8; m++) {
        int nl = nb + m;
        int n = node0 + nl;
        if (n < N_NODES) {
            float4 sv = *(const float4*)&g_S[(size_t)n * KDIM + c];
            float4 xv = *(const float4*)&Xin[(size_t)n * KDIM + c];
            sA[(c + 0) * ROWP + nl] = sv.x + xv.x;
            sA[(c + 1) * ROWP + nl] = sv.y + xv.y;
            sA[(c + 2) * ROWP + nl] = sv.z + xv.z;
            sA[(c + 3) * ROWP + nl] = sv.w + xv.w;
            sB[(c + 0) * ROWP + nl] = sv.x * xv.x;
            sB[(c + 1) * ROWP + nl] = sv.y * xv.y;
            sB[(c + 2) * ROWP + nl] = sv.z * xv.z;
            sB[(c + 3) * ROWP + nl] = sv.w * xv.w;
        } else {
            sA[(c + 0) * ROWP + nl] = 0.0f;
            sA[(c + 1) * ROWP + nl] = 0.0f;
            sA[(c + 2) * ROWP + nl] = 0.0f;
            sA[(c + 3) * ROWP + nl] = 0.0f;
            sB[(c + 0) * ROWP + nl] = 0.0f;
            sB[(c + 1) * ROWP + nl] = 0.0f;
            sB[(c + 2) * ROWP + nl] = 0.0f;
            sB[(c + 3) * ROWP + nl] = 0.0f;
        }
    }
    __syncwarp();

    float4 B1 = __ldg((const float4*)&b1[l * 64 + c]);
    float4 B2 = __ldg((const float4*)&b2[l * 64 + c]);

    u64 acc[4][4];
#pragma unroll
    for (int p = 0; p < 4; p++) {
        int n0 = node0 + nb + 2 * p;
        float w0 = (n0 < N_NODES) ? g_wsum[n0] : 0.0f;
        float w1 = (n0 + 1 < N_NODES) ? g_wsum[n0 + 1] : 0.0f;
        acc[p][0] = pack2((w0 + 1.0f) * B1.x + w0 * B2.x, (w1 + 1.0f) * B1.x + w1 * B2.x);
        acc[p][1] = pack2((w0 + 1.0f) * B1.y + w0 * B2.y, (w1 + 1.0f) * B1.y + w1 * B2.y);
        acc[p][2] = pack2((w0 + 1.0f) * B1.z + w0 * B2.z, (w1 + 1.0f) * B1.z + w1 * B2.z);
        acc[p][3] = pack2((w0 + 1.0f) * B1.w + w0 * B2.w, (w1 + 1.0f) * B1.w + w1 * B2.w);
    }

#pragma unroll 2
    for (int k = 0; k < 64; k++) {
        float4 w1 = __ldg((const float4*)&W1l[k * 64 + c]);
        float4 w2 = __ldg((const float4*)&W2l[k * 64 + c]);
        u64 d10 = dup2(w1.x), d11 = dup2(w1.y), d12 = dup2(w1.z), d13 = dup2(w1.w);
        u64 d20 = dup2(w2.x), d21 = dup2(w2.y), d22 = dup2(w2.z), d23 = dup2(w2.w);
        const float* ra = &sA[k * ROWP + nb];
        const float* rb = &sB[k * ROWP + nb];
#pragma unroll
        for (int p = 0; p < 4; p++) {
            u64 ap = *(const u64*)&ra[2 * p];
            u64 bp = *(const u64*)&rb[2 * p];
            fma2(acc[p][0], ap, d10);
            fma2(acc[p][1], ap, d11);
            fma2(acc[p][2], ap, d12);
            fma2(acc[p][3], ap, d13);
            fma2(acc[p][0], bp, d20);
            fma2(acc[p][1], bp, d21);
            fma2(acc[p][2], bp, d22);
            fma2(acc[p][3], bp, d23);
        }
    }

#pragma unroll
    for (int p = 0; p < 4; p++) {
        float2 y[4];
#pragma unroll
        for (int j = 0; j < 4; j++) {
            float2 v = unpack2(acc[p][j]);
            y[j].x = v.x > 0.0f ? v.x : NEG_SLOPE * v.x;
            y[j].y = v.y > 0.0f ? v.y : NEG_SLOPE * v.y;
        }
        float ssx = y[0].x * y[0].x + y[1].x * y[1].x + y[2].x * y[2].x + y[3].x * y[3].x;
        float ssy = y[0].y * y[0].y + y[1].y * y[1].y + y[2].y * y[2].y + y[3].y * y[3].y;
#pragma unroll
        for (int o = 1; o < 16; o <<= 1) {
            ssx += __shfl_xor_sync(0xffffffffu, ssx, o);
            ssy += __shfl_xor_sync(0xffffffffu, ssy, o);
        }
        float inv0 = 1.0f / fmaxf(sqrtf(ssx), EPSV);
        float inv1 = 1.0f / fmaxf(sqrtf(ssy), EPSV);
        int n0 = node0 + nb + 2 * p;
        if (n0 < N_NODES)
            *(float4*)&Yout[(size_t)n0 * KDIM + c] =
                make_float4(y[0].x * inv0, y[1].x * inv0, y[2].x * inv0, y[3].x * inv0);
        if (n0 + 1 < N_NODES)
            *(float4*)&Yout[(size_t)(n0 + 1) * KDIM + c] =
                make_float4(y[0].y * inv1, y[1].y * inv1, y[2].y * inv1, y[3].y * inv1);
    }
}

// ---------------- standalone final dot --------------------------------------
__global__ void k_dot(const int* __restrict__ user, const int* __restrict__ pos,
                      float* __restrict__ out, int sel, int first) {
    const float* __restrict__ X = sel ? g_Y : g_X;
    int gthr = blockIdx.x * blockDim.x + threadIdx.x;
    int w = gthr >> 5;
    if (w >= BATCH) return;
    int lane = threadIdx.x & 31;
    int u  = user[w];
    int it = pos[w];
    float2 a = *(const float2*)&X[(size_t)u * KDIM + lane * 2];
    float2 b = *(const float2*)&X[((size_t)N_USERS + it) * KDIM + lane * 2];
    float d = a.x * b.x + a.y * b.y;
    d += __shfl_xor_sync(0xffffffffu, d, 16);
    d += __shfl_xor_sync(0xffffffffu, d, 8);
    d += __shfl_xor_sync(0xffffffffu, d, 4);
    d += __shfl_xor_sync(0xffffffffu, d, 2);
    d += __shfl_xor_sync(0xffffffffu, d, 1);
    if (lane == 0) out[w] = first ? d : out[w] + d;
}

// ---------------- launch ----------------------------------------------------
extern "C" void kernel_launch(void* const* d_in, const int* in_sizes, int n_in,
                              void* d_out, int out_size) {
    const float* Gu   = (const float*)d_in[0];
    const float* Gi   = (const float*)d_in[1];
    const float* W1   = (const float*)d_in[2];
    const float* b1   = (const float*)d_in[3];
    const float* W2   = (const float*)d_in[4];
    const float* b2   = (const float*)d_in[5];
    const float* ew   = (const float*)d_in[6];
    const int*   esrc = (const int*)d_in[7];
    const int*   edst = (const int*)d_in[8];
    const int*   user = (const int*)d_in[9];
    const int*   pos  = (const int*)d_in[10];
    float* out = (float*)d_out;

    const int TB = 256;
    k_init<<<(N_NODES * KDIM / 4 + TB - 1) / TB, TB>>>(Gu, Gi);
    k_hist<<<(N_EDGES / 4 + TB - 1) / TB, TB>>>(edst);
    k_scan37<<<SCAN_BLOCKS, 1024>>>();
    k_fill<<<(N_EDGES / 4 + TB - 1) / TB, TB>>>(esrc, edst, ew);

    for (int l = 0; l < 3; l++) {
        int insel = l & 1;
        // gather for layer l + dot over layer-l input embeddings
        k_gather<<<GB_GATHER + DOT_BLOCKS, TB>>>(insel, user, pos, out, l == 0);
        k_update<<<(N_NODES + 63) / 64, 128>>>(W1, b1, W2, b2, l);
    }
    // final dot over layer-2 output (g_Y)
    k_dot<<<(BATCH * 32 + TB - 1) / TB, TB>>>(user, pos, out, 1, 0);
}